// round 1
// baseline (speedup 1.0000x reference)
#include <cuda_runtime.h>
#include <math.h>

#define N_NODES  50000
#define N_GRAPHS 500
#define N_EDGES  800000
#define D        128
#define HG_LD    (3 * D)   // 384

// ---------------- scratch (no allocs allowed) ----------------
__device__ float g_h[N_NODES * D];        // intermediate node features
__device__ float g_agg[N_NODES * D];      // aggregation buffer
__device__ float g_out_inv[N_NODES];
__device__ float g_in_inv[N_NODES];
__device__ float g_deg_out[N_NODES];
__device__ float g_deg_in[N_NODES];

// ---------------- init: zero degs + hg region ----------------
__global__ void zero_misc_kernel(float* __restrict__ hg) {
    int i = blockIdx.x * blockDim.x + threadIdx.x;
    int n = N_GRAPHS * HG_LD;                  // 192000 > N_NODES? no, 192000 vs 50000
    for (int idx = i; idx < n || idx < N_NODES; idx += gridDim.x * blockDim.x) {
        if (idx < N_NODES) { g_deg_out[idx] = 0.f; g_deg_in[idx] = 0.f; }
        if (idx < n) hg[idx] = 0.f;
    }
}

__global__ void degree_kernel(const int* __restrict__ src, const int* __restrict__ dst) {
    int i = blockIdx.x * blockDim.x + threadIdx.x;
    if (i < N_EDGES) {
        atomicAdd(&g_deg_out[src[i]], 1.0f);
        atomicAdd(&g_deg_in[dst[i]], 1.0f);
    }
}

__global__ void inv_kernel() {
    int i = blockIdx.x * blockDim.x + threadIdx.x;
    if (i < N_NODES) {
        g_out_inv[i] = rsqrtf(fmaxf(g_deg_out[i], 1.0f));
        g_in_inv[i]  = rsqrtf(fmaxf(g_deg_in[i], 1.0f));
    }
}

__global__ void zero_agg_kernel() {
    int i = blockIdx.x * blockDim.x + threadIdx.x;
    float4* p = reinterpret_cast<float4*>(g_agg);
    if (i < N_NODES * D / 4) p[i] = make_float4(0.f, 0.f, 0.f, 0.f);
}

// ---------------- edge scatter: agg[dst] += X[src] * out_inv[src] ----------------
// One warp per edge: 32 lanes x float4 = 128 floats.
__global__ void scatter_kernel(const float* __restrict__ X,
                               const int* __restrict__ src,
                               const int* __restrict__ dst) {
    int gtid = blockIdx.x * blockDim.x + threadIdx.x;
    int e    = gtid >> 5;
    int lane = gtid & 31;
    if (e >= N_EDGES) return;
    int s = __ldg(&src[e]);
    int d = __ldg(&dst[e]);
    float w = g_out_inv[s];
    float4 v = reinterpret_cast<const float4*>(X)[s * (D / 4) + lane];
    float* out = &g_agg[d * D + lane * 4];
    atomicAdd(out + 0, v.x * w);
    atomicAdd(out + 1, v.y * w);
    atomicAdd(out + 2, v.z * w);
    atomicAdd(out + 3, v.w * w);
}

// ---------------- fused GEMM + PReLU + graph pooling ----------------
// h = prelu( (agg * in_inv) @ W );  hg[g] += h
// Block: 256 threads, 64 rows x 128 cols tile; thread = 4 rows x 8 cols.
#define TM 64
#define XLD 132   // padded x-tile stride to kill smem bank conflicts

__global__ void __launch_bounds__(256)
gemm_prelu_pool_kernel(const float* __restrict__ W,
                       const float* __restrict__ a_ptr,
                       const int* __restrict__ graph_id,
                       float* __restrict__ Hout,
                       float* __restrict__ hg,
                       int hg_col_off) {
    extern __shared__ float sm[];
    float* Ws = sm;              // D*D floats (64 KB)
    float* Xs = sm + D * D;      // TM*XLD floats

    int tid  = threadIdx.x;
    int row0 = blockIdx.x * TM;

    // stage W (row-major [k][c])
    {
        float4* Ws4 = reinterpret_cast<float4*>(Ws);
        const float4* W4 = reinterpret_cast<const float4*>(W);
        #pragma unroll
        for (int i = tid; i < D * D / 4; i += 256) Ws4[i] = W4[i];
    }
    // stage X tile = agg[row] * in_inv[row]
    {
        const float4* X4 = reinterpret_cast<const float4*>(g_agg);
        for (int i = tid; i < TM * (D / 4); i += 256) {
            int r  = i >> 5;
            int k4 = i & 31;
            int row = row0 + r;
            float4 v = make_float4(0.f, 0.f, 0.f, 0.f);
            if (row < N_NODES) {
                v = X4[row * (D / 4) + k4];
                float s = g_in_inv[row];
                v.x *= s; v.y *= s; v.z *= s; v.w *= s;
            }
            *reinterpret_cast<float4*>(&Xs[r * XLD + k4 * 4]) = v;
        }
    }
    __syncthreads();

    int rg = tid >> 4;   // 0..15 -> rows rg*4 .. rg*4+3
    int cg = tid & 15;   // 0..15 -> cols cg*8 .. cg*8+7

    float acc[4][8];
    #pragma unroll
    for (int i = 0; i < 4; i++)
        #pragma unroll
        for (int j = 0; j < 8; j++) acc[i][j] = 0.f;

    #pragma unroll 4
    for (int k = 0; k < D; k++) {
        float xv[4];
        #pragma unroll
        for (int i = 0; i < 4; i++) xv[i] = Xs[(rg * 4 + i) * XLD + k];
        float4 wa = *reinterpret_cast<float4*>(&Ws[k * D + cg * 8]);
        float4 wb = *reinterpret_cast<float4*>(&Ws[k * D + cg * 8 + 4]);
        #pragma unroll
        for (int i = 0; i < 4; i++) {
            acc[i][0] += xv[i] * wa.x;
            acc[i][1] += xv[i] * wa.y;
            acc[i][2] += xv[i] * wa.z;
            acc[i][3] += xv[i] * wa.w;
            acc[i][4] += xv[i] * wb.x;
            acc[i][5] += xv[i] * wb.y;
            acc[i][6] += xv[i] * wb.z;
            acc[i][7] += xv[i] * wb.w;
        }
    }

    float alpha = __ldg(a_ptr);
    int colbase = cg * 8;

    int   grow[4];
    bool  valid[4];
    #pragma unroll
    for (int i = 0; i < 4; i++) {
        int row = row0 + rg * 4 + i;
        valid[i] = (row < N_NODES);
        grow[i]  = valid[i] ? __ldg(&graph_id[row]) : -1;
    }

    // PReLU + store h
    float hv[4][8];
    #pragma unroll
    for (int i = 0; i < 4; i++) {
        #pragma unroll
        for (int j = 0; j < 8; j++) {
            float z = acc[i][j];
            hv[i][j] = z > 0.f ? z : alpha * z;
        }
        if (valid[i]) {
            int row = row0 + rg * 4 + i;
            float4 s0 = make_float4(hv[i][0], hv[i][1], hv[i][2], hv[i][3]);
            float4 s1 = make_float4(hv[i][4], hv[i][5], hv[i][6], hv[i][7]);
            *reinterpret_cast<float4*>(&Hout[row * D + colbase])     = s0;
            *reinterpret_cast<float4*>(&Hout[row * D + colbase + 4]) = s1;
        }
    }

    // graph pooling: collapse 4 rows when same graph (typical: graphs ~100 rows)
    bool same = valid[0] & valid[3] & (grow[0] == grow[1]) & (grow[1] == grow[2]) & (grow[2] == grow[3]);
    if (same) {
        float* base = &hg[grow[0] * HG_LD + hg_col_off + colbase];
        #pragma unroll
        for (int j = 0; j < 8; j++) {
            float s = hv[0][j] + hv[1][j] + hv[2][j] + hv[3][j];
            atomicAdd(base + j, s);
        }
    } else {
        #pragma unroll
        for (int i = 0; i < 4; i++) {
            if (!valid[i]) continue;
            float* base = &hg[grow[i] * HG_LD + hg_col_off + colbase];
            #pragma unroll
            for (int j = 0; j < 8; j++) atomicAdd(base + j, hv[i][j]);
        }
    }
}

// ---------------- launch ----------------
extern "C" void kernel_launch(void* const* d_in, const int* in_sizes, int n_in,
                              void* d_out, int out_size) {
    const float* feat = (const float*)d_in[0];
    const float* W0   = (const float*)d_in[1];
    const float* W1   = (const float*)d_in[2];
    const float* W2   = (const float*)d_in[3];
    const float* a0   = (const float*)d_in[4];
    const float* a1   = (const float*)d_in[5];
    const float* a2   = (const float*)d_in[6];
    const int*   src  = (const int*)d_in[7];
    const int*   dst  = (const int*)d_in[8];
    const int*   gid  = (const int*)d_in[9];

    float* out_h  = (float*)d_out;                 // [N_NODES, D]
    float* out_hg = (float*)d_out + N_NODES * D;   // [N_GRAPHS, 3*D]

    void* h_sym = nullptr;
    cudaGetSymbolAddress(&h_sym, g_h);
    float* h_buf = (float*)h_sym;

    const int smem_bytes = (D * D + TM * XLD) * sizeof(float);
    static bool attr_set = false;
    if (!attr_set) {
        cudaFuncSetAttribute(gemm_prelu_pool_kernel,
                             cudaFuncAttributeMaxDynamicSharedMemorySize, smem_bytes);
        attr_set = true;
    }

    // init
    {
        int n = N_GRAPHS * HG_LD;
        zero_misc_kernel<<<(n + 255) / 256, 256>>>(out_hg);
        degree_kernel<<<(N_EDGES + 255) / 256, 256>>>(src, dst);
        inv_kernel<<<(N_NODES + 255) / 256, 256>>>();
    }

    const float* Ws[3] = {W0, W1, W2};
    const float* as[3] = {a0, a1, a2};
    const float* Xin   = feat;

    int scatter_blocks = (N_EDGES * 32 + 255) / 256;
    int zero_blocks    = (N_NODES * D / 4 + 255) / 256;
    int gemm_blocks    = (N_NODES + TM - 1) / TM;

    for (int l = 0; l < 3; l++) {
        zero_agg_kernel<<<zero_blocks, 256>>>();
        scatter_kernel<<<scatter_blocks, 256>>>(Xin, src, dst);
        float* Hout = (l == 2) ? out_h : h_buf;
        gemm_prelu_pool_kernel<<<gemm_blocks, 256, smem_bytes>>>(
            Ws[l], as[l], gid, Hout, out_hg, l * D);
        Xin = h_buf;
    }
}

// round 2
// speedup vs baseline: 2.3691x; 2.3691x over previous
#include <cuda_runtime.h>
#include <math.h>

#define N_NODES  50000
#define N_GRAPHS 500
#define N_EDGES  800000
#define D        128
#define HG_LD    (3 * D)   // 384

// ---------------- scratch (no allocs allowed) ----------------
__device__ float g_h[N_NODES * D];        // intermediate node features
__device__ float g_agg[N_NODES * D];      // aggregation buffer (scaled by in_inv)
__device__ float g_out_inv[N_NODES];
__device__ float g_in_inv[N_NODES];
__device__ int   g_deg_out[N_NODES];
__device__ int   g_deg_in[N_NODES];
__device__ int   g_off[N_NODES + 1];      // CSR offsets by dst
__device__ int   g_cursor[N_NODES];       // fill cursors
__device__ int2  g_edges[N_EDGES];        // {src, out_inv[src] bits}

// ---------------- init: zero degs + hg region ----------------
__global__ void zero_misc_kernel(float* __restrict__ hg) {
    int i = blockIdx.x * blockDim.x + threadIdx.x;
    const int n = N_GRAPHS * HG_LD;   // 192000
    for (int idx = i; idx < n; idx += gridDim.x * blockDim.x) {
        if (idx < N_NODES) { g_deg_out[idx] = 0; g_deg_in[idx] = 0; }
        hg[idx] = 0.f;
    }
}

__global__ void degree_kernel(const int* __restrict__ src, const int* __restrict__ dst) {
    int i = blockIdx.x * blockDim.x + threadIdx.x;
    if (i < N_EDGES) {
        atomicAdd(&g_deg_out[src[i]], 1);
        atomicAdd(&g_deg_in[dst[i]], 1);
    }
}

__global__ void inv_kernel() {
    int i = blockIdx.x * blockDim.x + threadIdx.x;
    if (i < N_NODES) {
        g_out_inv[i] = rsqrtf(fmaxf((float)g_deg_out[i], 1.0f));
        g_in_inv[i]  = rsqrtf(fmaxf((float)g_deg_in[i], 1.0f));
    }
}

// ---------------- single-block exclusive scan of deg_in -> off/cursor ----------------
#define SCAN_T 1024
__global__ void __launch_bounds__(SCAN_T)
scan_kernel() {
    __shared__ int wsum[32];
    __shared__ int carry_s;
    int lane = threadIdx.x & 31;
    int wid  = threadIdx.x >> 5;
    if (threadIdx.x == 0) carry_s = 0;
    __syncthreads();

    for (int base = 0; base < N_NODES; base += SCAN_T) {
        int i = base + threadIdx.x;
        int v = (i < N_NODES) ? g_deg_in[i] : 0;
        // warp inclusive scan
        int incl = v;
        #pragma unroll
        for (int o = 1; o < 32; o <<= 1) {
            int t = __shfl_up_sync(0xFFFFFFFF, incl, o);
            if (lane >= o) incl += t;
        }
        if (lane == 31) wsum[wid] = incl;
        __syncthreads();
        if (wid == 0) {
            int t = wsum[lane];
            int s = t;
            #pragma unroll
            for (int o = 1; o < 32; o <<= 1) {
                int u = __shfl_up_sync(0xFFFFFFFF, s, o);
                if (lane >= o) s += u;
            }
            wsum[lane] = s - t;   // exclusive warp-total prefix
        }
        __syncthreads();
        int carry = carry_s;
        int excl = incl - v + wsum[wid];
        if (i < N_NODES) {
            g_off[i]    = carry + excl;
            g_cursor[i] = carry + excl;
        }
        __syncthreads();
        if (threadIdx.x == SCAN_T - 1) carry_s = carry + excl + v;
        __syncthreads();
    }
    if (threadIdx.x == 0) g_off[N_NODES] = carry_s;
}

__global__ void fill_kernel(const int* __restrict__ src, const int* __restrict__ dst) {
    int e = blockIdx.x * blockDim.x + threadIdx.x;
    if (e < N_EDGES) {
        int s = src[e];
        int d = dst[e];
        int pos = atomicAdd(&g_cursor[d], 1);
        g_edges[pos] = make_int2(s, __float_as_int(g_out_inv[s]));
    }
}

// ---------------- pull-gather: agg[n] = in_inv[n] * sum_{e in N_in(n)} X[src]*out_inv[src]
// One warp per node. Each lane owns a float4 (4 cols).
__global__ void __launch_bounds__(256)
gather_kernel(const float* __restrict__ X) {
    int gtid = blockIdx.x * blockDim.x + threadIdx.x;
    int node = gtid >> 5;
    int lane = gtid & 31;
    if (node >= N_NODES) return;
    int beg = g_off[node];
    int end = g_off[node + 1];

    const float4* X4 = reinterpret_cast<const float4*>(X);
    float4 acc = make_float4(0.f, 0.f, 0.f, 0.f);

    int j = beg;
    for (; j + 4 <= end; j += 4) {
        int2 e0 = g_edges[j + 0];
        int2 e1 = g_edges[j + 1];
        int2 e2 = g_edges[j + 2];
        int2 e3 = g_edges[j + 3];
        float4 v0 = X4[e0.x * (D / 4) + lane];
        float4 v1 = X4[e1.x * (D / 4) + lane];
        float4 v2 = X4[e2.x * (D / 4) + lane];
        float4 v3 = X4[e3.x * (D / 4) + lane];
        float w0 = __int_as_float(e0.y);
        float w1 = __int_as_float(e1.y);
        float w2 = __int_as_float(e2.y);
        float w3 = __int_as_float(e3.y);
        acc.x += v0.x * w0; acc.y += v0.y * w0; acc.z += v0.z * w0; acc.w += v0.w * w0;
        acc.x += v1.x * w1; acc.y += v1.y * w1; acc.z += v1.z * w1; acc.w += v1.w * w1;
        acc.x += v2.x * w2; acc.y += v2.y * w2; acc.z += v2.z * w2; acc.w += v2.w * w2;
        acc.x += v3.x * w3; acc.y += v3.y * w3; acc.z += v3.z * w3; acc.w += v3.w * w3;
    }
    for (; j < end; j++) {
        int2 e = g_edges[j];
        float4 v = X4[e.x * (D / 4) + lane];
        float w = __int_as_float(e.y);
        acc.x += v.x * w; acc.y += v.y * w; acc.z += v.z * w; acc.w += v.w * w;
    }

    float s = g_in_inv[node];
    acc.x *= s; acc.y *= s; acc.z *= s; acc.w *= s;
    reinterpret_cast<float4*>(g_agg)[node * (D / 4) + lane] = acc;
}

// ---------------- fused GEMM + PReLU + graph pooling ----------------
// h = prelu( agg @ W );  hg[g] += h   (agg already includes in_inv)
#define TM 64
#define XLD 132   // padded x-tile stride to kill smem bank conflicts

__global__ void __launch_bounds__(256)
gemm_prelu_pool_kernel(const float* __restrict__ W,
                       const float* __restrict__ a_ptr,
                       const int* __restrict__ graph_id,
                       float* __restrict__ Hout,
                       float* __restrict__ hg,
                       int hg_col_off) {
    extern __shared__ float sm[];
    float* Ws = sm;              // D*D floats (64 KB)
    float* Xs = sm + D * D;      // TM*XLD floats

    int tid  = threadIdx.x;
    int row0 = blockIdx.x * TM;

    // stage W (row-major [k][c])
    {
        float4* Ws4 = reinterpret_cast<float4*>(Ws);
        const float4* W4 = reinterpret_cast<const float4*>(W);
        #pragma unroll
        for (int i = tid; i < D * D / 4; i += 256) Ws4[i] = W4[i];
    }
    // stage X tile from g_agg
    {
        const float4* X4 = reinterpret_cast<const float4*>(g_agg);
        for (int i = tid; i < TM * (D / 4); i += 256) {
            int r  = i >> 5;
            int k4 = i & 31;
            int row = row0 + r;
            float4 v = make_float4(0.f, 0.f, 0.f, 0.f);
            if (row < N_NODES) v = X4[row * (D / 4) + k4];
            *reinterpret_cast<float4*>(&Xs[r * XLD + k4 * 4]) = v;
        }
    }
    __syncthreads();

    int rg = tid >> 4;   // 0..15 -> rows rg*4 .. rg*4+3
    int cg = tid & 15;   // 0..15 -> cols cg*8 .. cg*8+7

    float acc[4][8];
    #pragma unroll
    for (int i = 0; i < 4; i++)
        #pragma unroll
        for (int j = 0; j < 8; j++) acc[i][j] = 0.f;

    #pragma unroll 4
    for (int k = 0; k < D; k++) {
        float xv[4];
        #pragma unroll
        for (int i = 0; i < 4; i++) xv[i] = Xs[(rg * 4 + i) * XLD + k];
        float4 wa = *reinterpret_cast<float4*>(&Ws[k * D + cg * 8]);
        float4 wb = *reinterpret_cast<float4*>(&Ws[k * D + cg * 8 + 4]);
        #pragma unroll
        for (int i = 0; i < 4; i++) {
            acc[i][0] += xv[i] * wa.x;
            acc[i][1] += xv[i] * wa.y;
            acc[i][2] += xv[i] * wa.z;
            acc[i][3] += xv[i] * wa.w;
            acc[i][4] += xv[i] * wb.x;
            acc[i][5] += xv[i] * wb.y;
            acc[i][6] += xv[i] * wb.z;
            acc[i][7] += xv[i] * wb.w;
        }
    }

    float alpha = __ldg(a_ptr);
    int colbase = cg * 8;

    int   grow[4];
    bool  valid[4];
    #pragma unroll
    for (int i = 0; i < 4; i++) {
        int row = row0 + rg * 4 + i;
        valid[i] = (row < N_NODES);
        grow[i]  = valid[i] ? __ldg(&graph_id[row]) : -1;
    }

    // PReLU + store h
    float hv[4][8];
    #pragma unroll
    for (int i = 0; i < 4; i++) {
        #pragma unroll
        for (int j = 0; j < 8; j++) {
            float z = acc[i][j];
            hv[i][j] = z > 0.f ? z : alpha * z;
        }
        if (valid[i]) {
            int row = row0 + rg * 4 + i;
            float4 s0 = make_float4(hv[i][0], hv[i][1], hv[i][2], hv[i][3]);
            float4 s1 = make_float4(hv[i][4], hv[i][5], hv[i][6], hv[i][7]);
            *reinterpret_cast<float4*>(&Hout[row * D + colbase])     = s0;
            *reinterpret_cast<float4*>(&Hout[row * D + colbase + 4]) = s1;
        }
    }

    // graph pooling: collapse 4 rows when same graph (typical: graphs ~100 rows)
    bool same = valid[0] & valid[3] & (grow[0] == grow[1]) & (grow[1] == grow[2]) & (grow[2] == grow[3]);
    if (same) {
        float* base = &hg[grow[0] * HG_LD + hg_col_off + colbase];
        #pragma unroll
        for (int j = 0; j < 8; j++) {
            float s = hv[0][j] + hv[1][j] + hv[2][j] + hv[3][j];
            atomicAdd(base + j, s);
        }
    } else {
        #pragma unroll
        for (int i = 0; i < 4; i++) {
            if (!valid[i]) continue;
            float* base = &hg[grow[i] * HG_LD + hg_col_off + colbase];
            #pragma unroll
            for (int j = 0; j < 8; j++) atomicAdd(base + j, hv[i][j]);
        }
    }
}

// ---------------- launch ----------------
extern "C" void kernel_launch(void* const* d_in, const int* in_sizes, int n_in,
                              void* d_out, int out_size) {
    const float* feat = (const float*)d_in[0];
    const float* W0   = (const float*)d_in[1];
    const float* W1   = (const float*)d_in[2];
    const float* W2   = (const float*)d_in[3];
    const float* a0   = (const float*)d_in[4];
    const float* a1   = (const float*)d_in[5];
    const float* a2   = (const float*)d_in[6];
    const int*   src  = (const int*)d_in[7];
    const int*   dst  = (const int*)d_in[8];
    const int*   gid  = (const int*)d_in[9];

    float* out_h  = (float*)d_out;                 // [N_NODES, D]
    float* out_hg = (float*)d_out + N_NODES * D;   // [N_GRAPHS, 3*D]

    void* h_sym = nullptr;
    cudaGetSymbolAddress(&h_sym, g_h);
    float* h_buf = (float*)h_sym;

    const int smem_bytes = (D * D + TM * XLD) * sizeof(float);
    static bool attr_set = false;
    if (!attr_set) {
        cudaFuncSetAttribute(gemm_prelu_pool_kernel,
                             cudaFuncAttributeMaxDynamicSharedMemorySize, smem_bytes);
        attr_set = true;
    }

    // ---- build CSR (by dst) + norms, every call (graph-capturable) ----
    {
        int n = N_GRAPHS * HG_LD;
        zero_misc_kernel<<<(n + 255) / 256, 256>>>(out_hg);
        degree_kernel<<<(N_EDGES + 255) / 256, 256>>>(src, dst);
        scan_kernel<<<1, SCAN_T>>>();
        inv_kernel<<<(N_NODES + 255) / 256, 256>>>();
        fill_kernel<<<(N_EDGES + 255) / 256, 256>>>(src, dst);
    }

    const float* Ws[3] = {W0, W1, W2};
    const float* as[3] = {a0, a1, a2};
    const float* Xin   = feat;

    int gather_blocks = (N_NODES * 32 + 255) / 256;
    int gemm_blocks   = (N_NODES + TM - 1) / TM;

    for (int l = 0; l < 3; l++) {
        gather_kernel<<<gather_blocks, 256>>>(Xin);
        float* Hout = (l == 2) ? out_h : h_buf;
        gemm_prelu_pool_kernel<<<gemm_blocks, 256, smem_bytes>>>(
            Ws[l], as[l], gid, Hout, out_hg, l * D);
        Xin = h_buf;
    }
}

// round 4
// speedup vs baseline: 2.3695x; 1.0002x over previous
#include <cuda_runtime.h>
#include <math.h>

#define N_NODES  50000
#define N_GRAPHS 500
#define N_EDGES  800000
#define D        128
#define HG_LD    (3 * D)   // 384

// ---------------- scratch (no allocs allowed) ----------------
__device__ float g_h[N_NODES * D];        // intermediate node features
__device__ float g_agg[N_NODES * D];      // aggregation buffer (scaled by in_inv)
__device__ float g_out_inv[N_NODES];
__device__ float g_in_inv[N_NODES];
__device__ int   g_deg_out[N_NODES];
__device__ int   g_deg_in[N_NODES];
__device__ int   g_off[N_NODES + 1];      // CSR offsets by dst
__device__ int   g_cursor[N_NODES];       // fill cursors
__device__ int2  g_edges[N_EDGES];        // {src, out_inv[src] bits}

// ---------------- packed f32x2 helpers (FFMA2 — PTX-only on Blackwell) ----------------
__device__ __forceinline__ void ffma2(unsigned long long& acc,
                                      unsigned long long x,
                                      unsigned long long w) {
    asm("fma.rn.f32x2 %0, %1, %2, %0;" : "+l"(acc) : "l"(x), "l"(w));
}
__device__ __forceinline__ unsigned long long bc2(float x) {
    unsigned long long r;
    asm("mov.b64 %0, {%1, %1};" : "=l"(r) : "f"(x));
    return r;
}
__device__ __forceinline__ float2 unpk2(unsigned long long v) {
    float2 r;
    asm("mov.b64 {%0, %1}, %2;" : "=f"(r.x), "=f"(r.y) : "l"(v));
    return r;
}

// ---------------- init: zero degs + hg region ----------------
__global__ void zero_misc_kernel(float* __restrict__ hg) {
    int i = blockIdx.x * blockDim.x + threadIdx.x;
    const int n = N_GRAPHS * HG_LD;   // 192000
    for (int idx = i; idx < n; idx += gridDim.x * blockDim.x) {
        if (idx < N_NODES) { g_deg_out[idx] = 0; g_deg_in[idx] = 0; }
        hg[idx] = 0.f;
    }
}

__global__ void degree_kernel(const int* __restrict__ src, const int* __restrict__ dst) {
    int i = blockIdx.x * blockDim.x + threadIdx.x;
    if (i < N_EDGES) {
        atomicAdd(&g_deg_out[src[i]], 1);
        atomicAdd(&g_deg_in[dst[i]], 1);
    }
}

__global__ void inv_kernel() {
    int i = blockIdx.x * blockDim.x + threadIdx.x;
    if (i < N_NODES) {
        g_out_inv[i] = rsqrtf(fmaxf((float)g_deg_out[i], 1.0f));
        g_in_inv[i]  = rsqrtf(fmaxf((float)g_deg_in[i], 1.0f));
    }
}

// ---------------- single-block exclusive scan of deg_in -> off/cursor ----------------
#define SCAN_T 1024
__global__ void __launch_bounds__(SCAN_T)
scan_kernel() {
    __shared__ int wsum[32];
    __shared__ int carry_s;
    int lane = threadIdx.x & 31;
    int wid  = threadIdx.x >> 5;
    if (threadIdx.x == 0) carry_s = 0;
    __syncthreads();

    for (int base = 0; base < N_NODES; base += SCAN_T) {
        int i = base + threadIdx.x;
        int v = (i < N_NODES) ? g_deg_in[i] : 0;
        int incl = v;
        #pragma unroll
        for (int o = 1; o < 32; o <<= 1) {
            int t = __shfl_up_sync(0xFFFFFFFF, incl, o);
            if (lane >= o) incl += t;
        }
        if (lane == 31) wsum[wid] = incl;
        __syncthreads();
        if (wid == 0) {
            int t = wsum[lane];
            int s = t;
            #pragma unroll
            for (int o = 1; o < 32; o <<= 1) {
                int u = __shfl_up_sync(0xFFFFFFFF, s, o);
                if (lane >= o) s += u;
            }
            wsum[lane] = s - t;   // exclusive warp-total prefix
        }
        __syncthreads();
        int carry = carry_s;
        int excl = incl - v + wsum[wid];
        if (i < N_NODES) {
            g_off[i]    = carry + excl;
            g_cursor[i] = carry + excl;
        }
        __syncthreads();
        if (threadIdx.x == SCAN_T - 1) carry_s = carry + excl + v;
        __syncthreads();
    }
    if (threadIdx.x == 0) g_off[N_NODES] = carry_s;
}

__global__ void fill_kernel(const int* __restrict__ src, const int* __restrict__ dst) {
    int e = blockIdx.x * blockDim.x + threadIdx.x;
    if (e < N_EDGES) {
        int s = src[e];
        int d = dst[e];
        int pos = atomicAdd(&g_cursor[d], 1);
        g_edges[pos] = make_int2(s, __float_as_int(g_out_inv[s]));
    }
}

// ---------------- pull-gather: agg[n] = in_inv[n] * sum X[src]*out_inv[src] ----------------
// One warp per node; each lane owns a float4 (4 cols). Unroll-8 for MLP.
__global__ void __launch_bounds__(256)
gather_kernel(const float* __restrict__ X) {
    int gtid = blockIdx.x * blockDim.x + threadIdx.x;
    int node = gtid >> 5;
    int lane = gtid & 31;
    if (node >= N_NODES) return;
    int beg = g_off[node];
    int end = g_off[node + 1];

    const float4* X4 = reinterpret_cast<const float4*>(X);
    float4 acc = make_float4(0.f, 0.f, 0.f, 0.f);

    int j = beg;
    for (; j + 8 <= end; j += 8) {
        int2 e[8];
        #pragma unroll
        for (int t = 0; t < 8; t++) e[t] = g_edges[j + t];
        float4 v[8];
        #pragma unroll
        for (int t = 0; t < 8; t++) v[t] = X4[e[t].x * (D / 4) + lane];
        #pragma unroll
        for (int t = 0; t < 8; t++) {
            float w = __int_as_float(e[t].y);
            acc.x += v[t].x * w; acc.y += v[t].y * w;
            acc.z += v[t].z * w; acc.w += v[t].w * w;
        }
    }
    if (j + 4 <= end) {
        int2 e[4];
        #pragma unroll
        for (int t = 0; t < 4; t++) e[t] = g_edges[j + t];
        float4 v[4];
        #pragma unroll
        for (int t = 0; t < 4; t++) v[t] = X4[e[t].x * (D / 4) + lane];
        #pragma unroll
        for (int t = 0; t < 4; t++) {
            float w = __int_as_float(e[t].y);
            acc.x += v[t].x * w; acc.y += v[t].y * w;
            acc.z += v[t].z * w; acc.w += v[t].w * w;
        }
        j += 4;
    }
    for (; j < end; j++) {
        int2 e = g_edges[j];
        float4 v = X4[e.x * (D / 4) + lane];
        float w = __int_as_float(e.y);
        acc.x += v.x * w; acc.y += v.y * w; acc.z += v.z * w; acc.w += v.w * w;
    }

    float s = g_in_inv[node];
    acc.x *= s; acc.y *= s; acc.z *= s; acc.w *= s;
    reinterpret_cast<float4*>(g_agg)[node * (D / 4) + lane] = acc;
}

// ---------------- fused GEMM + PReLU + graph pooling (FFMA2 inner loop) ----------------
// h = prelu( agg @ W );  hg[g] += h   (agg already includes in_inv)
#define TM 64
#define XLD 132   // padded x-tile stride (132*4B = 528B, 16B-aligned rows)

__global__ void __launch_bounds__(256)
gemm_prelu_pool_kernel(const float* __restrict__ W,
                       const float* __restrict__ a_ptr,
                       const int* __restrict__ graph_id,
                       float* __restrict__ Hout,
                       float* __restrict__ hg,
                       int hg_col_off) {
    extern __shared__ float sm[];
    float* Ws = sm;              // D*D floats (64 KB)
    float* Xs = sm + D * D;      // TM*XLD floats

    int tid  = threadIdx.x;
    int row0 = blockIdx.x * TM;

    // stage W (row-major [k][c])
    {
        float4* Ws4 = reinterpret_cast<float4*>(Ws);
        const float4* W4 = reinterpret_cast<const float4*>(W);
        #pragma unroll
        for (int i = tid; i < D * D / 4; i += 256) Ws4[i] = W4[i];
    }
    // stage X tile from g_agg
    {
        const float4* X4 = reinterpret_cast<const float4*>(g_agg);
        for (int i = tid; i < TM * (D / 4); i += 256) {
            int r  = i >> 5;
            int k4 = i & 31;
            int row = row0 + r;
            float4 v = make_float4(0.f, 0.f, 0.f, 0.f);
            if (row < N_NODES) v = X4[row * (D / 4) + k4];
            *reinterpret_cast<float4*>(&Xs[r * XLD + k4 * 4]) = v;
        }
    }
    __syncthreads();

    int rg = tid >> 4;   // 0..15 -> rows rg*4 .. rg*4+3
    int cg = tid & 15;   // 0..15 -> cols cg*8 .. cg*8+7

    // acc2[i][p] holds cols {2p, 2p+1} (within this thread's 8-col group) for row i
    unsigned long long acc2[4][4];
    #pragma unroll
    for (int i = 0; i < 4; i++)
        #pragma unroll
        for (int p = 0; p < 4; p++) acc2[i][p] = 0ull;

    #pragma unroll 4
    for (int k4 = 0; k4 < D / 4; k4++) {
        float xr[4][4];
        #pragma unroll
        for (int i = 0; i < 4; i++) {
            float4 t = *reinterpret_cast<const float4*>(&Xs[(rg * 4 + i) * XLD + k4 * 4]);
            xr[i][0] = t.x; xr[i][1] = t.y; xr[i][2] = t.z; xr[i][3] = t.w;
        }
        #pragma unroll
        for (int kk = 0; kk < 4; kk++) {
            int k = k4 * 4 + kk;
            const ulonglong2* wp =
                reinterpret_cast<const ulonglong2*>(&Ws[k * D + cg * 8]);
            ulonglong2 wa = wp[0];   // cols {0,1},{2,3}
            ulonglong2 wb = wp[1];   // cols {4,5},{6,7}
            #pragma unroll
            for (int i = 0; i < 4; i++) {
                unsigned long long x2 = bc2(xr[i][kk]);
                ffma2(acc2[i][0], x2, wa.x);
                ffma2(acc2[i][1], x2, wa.y);
                ffma2(acc2[i][2], x2, wb.x);
                ffma2(acc2[i][3], x2, wb.y);
            }
        }
    }

    float alpha = __ldg(a_ptr);
    int colbase = cg * 8;

    int   grow[4];
    bool  valid[4];
    #pragma unroll
    for (int i = 0; i < 4; i++) {
        int row = row0 + rg * 4 + i;
        valid[i] = (row < N_NODES);
        grow[i]  = valid[i] ? __ldg(&graph_id[row]) : -1;
    }

    // PReLU + store h
    float hv[4][8];
    #pragma unroll
    for (int i = 0; i < 4; i++) {
        #pragma unroll
        for (int p = 0; p < 4; p++) {
            float2 v = unpk2(acc2[i][p]);
            hv[i][2 * p]     = v.x > 0.f ? v.x : alpha * v.x;
            hv[i][2 * p + 1] = v.y > 0.f ? v.y : alpha * v.y;
        }
        if (valid[i]) {
            int row = row0 + rg * 4 + i;
            float4 s0 = make_float4(hv[i][0], hv[i][1], hv[i][2], hv[i][3]);
            float4 s1 = make_float4(hv[i][4], hv[i][5], hv[i][6], hv[i][7]);
            *reinterpret_cast<float4*>(&Hout[row * D + colbase])     = s0;
            *reinterpret_cast<float4*>(&Hout[row * D + colbase + 4]) = s1;
        }
    }

    // graph pooling: collapse 4 rows when same graph
    bool same = valid[0] & valid[3] & (grow[0] == grow[1]) & (grow[1] == grow[2]) & (grow[2] == grow[3]);
    if (same) {
        float* base = &hg[grow[0] * HG_LD + hg_col_off + colbase];
        #pragma unroll
        for (int j = 0; j < 8; j++) {
            float s = hv[0][j] + hv[1][j] + hv[2][j] + hv[3][j];
            atomicAdd(base + j, s);
        }
    } else {
        #pragma unroll
        for (int i = 0; i < 4; i++) {
            if (!valid[i]) continue;
            float* base = &hg[grow[i] * HG_LD + hg_col_off + colbase];
            #pragma unroll
            for (int j = 0; j < 8; j++) atomicAdd(base + j, hv[i][j]);
        }
    }
}

// ---------------- launch ----------------
extern "C" void kernel_launch(void* const* d_in, const int* in_sizes, int n_in,
                              void* d_out, int out_size) {
    const float* feat = (const float*)d_in[0];
    const float* W0   = (const float*)d_in[1];
    const float* W1   = (const float*)d_in[2];
    const float* W2   = (const float*)d_in[3];
    const float* a0   = (const float*)d_in[4];
    const float* a1   = (const float*)d_in[5];
    const float* a2   = (const float*)d_in[6];
    const int*   src  = (const int*)d_in[7];
    const int*   dst  = (const int*)d_in[8];
    const int*   gid  = (const int*)d_in[9];

    float* out_h  = (float*)d_out;                 // [N_NODES, D]
    float* out_hg = (float*)d_out + N_NODES * D;   // [N_GRAPHS, 3*D]

    void* h_sym = nullptr;
    cudaGetSymbolAddress(&h_sym, g_h);
    float* h_buf = (float*)h_sym;

    const int smem_bytes = (D * D + TM * XLD) * sizeof(float);
    static bool attr_set = false;
    if (!attr_set) {
        cudaFuncSetAttribute(gemm_prelu_pool_kernel,
                             cudaFuncAttributeMaxDynamicSharedMemorySize, smem_bytes);
        attr_set = true;
    }

    // ---- build CSR (by dst) + norms, every call (graph-capturable) ----
    {
        int n = N_GRAPHS * HG_LD;
        zero_misc_kernel<<<(n + 255) / 256, 256>>>(out_hg);
        degree_kernel<<<(N_EDGES + 255) / 256, 256>>>(src, dst);
        scan_kernel<<<1, SCAN_T>>>();
        inv_kernel<<<(N_NODES + 255) / 256, 256>>>();
        fill_kernel<<<(N_EDGES + 255) / 256, 256>>>(src, dst);
    }

    const float* Ws[3] = {W0, W1, W2};
    const float* as[3] = {a0, a1, a2};
    const float* Xin   = feat;

    int gather_blocks = (N_NODES * 32 + 255) / 256;
    int gemm_blocks   = (N_NODES + TM - 1) / TM;

    for (int l = 0; l < 3; l++) {
        gather_kernel<<<gather_blocks, 256>>>(Xin);
        float* Hout = (l == 2) ? out_h : h_buf;
        gemm_prelu_pool_kernel<<<gemm_blocks, 256, smem_bytes>>>(
            Ws[l], as[l], gid, Hout, out_hg, l * D);
        Xin = h_buf;
    }
}